// round 1
// baseline (speedup 1.0000x reference)
#include <cuda_runtime.h>
#include <math.h>

#define D_MODEL 1024
#define SEQ     2048
#define BATCH   4
#define NH      16
#define HD      64
#define DFF     4096
#define MROWS   (BATCH*SEQ)   /* 8192 */

// ---------------- scratch (device globals: allocation-free) ----------------
__device__ float g_ln [MROWS * D_MODEL];       // 32 MB (reused for ln1 and ln2 out)
__device__ float g_qkv[MROWS * 3 * D_MODEL];   // 96 MB
__device__ float g_ctx[MROWS * D_MODEL];       // 32 MB
__device__ float g_x1 [MROWS * D_MODEL];       // 32 MB
__device__ float g_h  [MROWS * DFF];           // 128 MB

// ---------------- LayerNorm ----------------
__device__ __forceinline__ float block_reduce_sum(float v, float* sbuf) {
    int lane = threadIdx.x & 31, wid = threadIdx.x >> 5;
    #pragma unroll
    for (int o = 16; o; o >>= 1) v += __shfl_xor_sync(0xffffffffu, v, o);
    if (lane == 0) sbuf[wid] = v;
    __syncthreads();
    if (wid == 0) {
        float r = (lane < 8) ? sbuf[lane] : 0.f;
        #pragma unroll
        for (int o = 4; o; o >>= 1) r += __shfl_xor_sync(0xffffffffu, r, o);
        if (lane == 0) sbuf[8] = r;
    }
    __syncthreads();
    float out = sbuf[8];
    __syncthreads();
    return out;
}

__global__ void __launch_bounds__(256) ln_kernel(
    const float* __restrict__ x, const float* __restrict__ sc,
    const float* __restrict__ bi, float* __restrict__ y)
{
    __shared__ float red[9];
    int row = blockIdx.x;
    int t = threadIdx.x;
    const float4 v = *reinterpret_cast<const float4*>(x + (size_t)row * D_MODEL + t * 4);
    float s = v.x + v.y + v.z + v.w;
    s = block_reduce_sum(s, red);
    float mu = s * (1.0f / D_MODEL);
    float d0 = v.x - mu, d1 = v.y - mu, d2 = v.z - mu, d3 = v.w - mu;
    float sq = d0*d0 + d1*d1 + d2*d2 + d3*d3;
    sq = block_reduce_sum(sq, red);
    float inv = rsqrtf(sq * (1.0f / D_MODEL) + 1e-6f);
    const float4 scv = *reinterpret_cast<const float4*>(sc + t * 4);
    const float4 biv = *reinterpret_cast<const float4*>(bi + t * 4);
    float4 o;
    o.x = d0 * inv * scv.x + biv.x;
    o.y = d1 * inv * scv.y + biv.y;
    o.z = d2 * inv * scv.z + biv.z;
    o.w = d3 * inv * scv.w + biv.w;
    *reinterpret_cast<float4*>(y + (size_t)row * D_MODEL + t * 4) = o;
}

// ---------------- SGEMM: C = A @ B + bias (+residual) (+gelu) ----------------
__device__ __forceinline__ float gelu_tanh(float x) {
    // jax.nn.gelu default (approximate=True)
    float x3 = x * x * x;
    return 0.5f * x * (1.0f + tanhf(0.7978845608028654f * (x + 0.044715f * x3)));
}

template<bool GELU, bool RES>
__global__ void __launch_bounds__(256) sgemm_kernel(
    const float* __restrict__ A, const float* __restrict__ B,
    const float* __restrict__ bias, const float* __restrict__ R,
    float* __restrict__ C, int M, int N, int K)
{
    __shared__ float As[8][128];
    __shared__ float Bs[8][128];
    const int tid = threadIdx.x;
    const int n0 = blockIdx.x * 128, m0 = blockIdx.y * 128;
    const int tx = tid & 15, ty = tid >> 4;
    const int arow = tid >> 1, ak = (tid & 1) * 4;
    const int brow = tid >> 5, bcol = (tid & 31) * 4;

    float c[8][8];
    #pragma unroll
    for (int i = 0; i < 8; i++)
        #pragma unroll
        for (int j = 0; j < 8; j++) c[i][j] = 0.f;

    const float* Aptr = A + (size_t)(m0 + arow) * K + ak;
    const float* Bptr = B + (size_t)brow * N + n0 + bcol;

    for (int k0 = 0; k0 < K; k0 += 8) {
        float4 av = *reinterpret_cast<const float4*>(Aptr + k0);
        As[ak + 0][arow] = av.x;
        As[ak + 1][arow] = av.y;
        As[ak + 2][arow] = av.z;
        As[ak + 3][arow] = av.w;
        *reinterpret_cast<float4*>(&Bs[brow][bcol]) =
            *reinterpret_cast<const float4*>(Bptr + (size_t)k0 * N);
        __syncthreads();
        #pragma unroll
        for (int k = 0; k < 8; k++) {
            float a[8], b[8];
            *reinterpret_cast<float4*>(a)     = *reinterpret_cast<float4*>(&As[k][ty * 8]);
            *reinterpret_cast<float4*>(a + 4) = *reinterpret_cast<float4*>(&As[k][ty * 8 + 4]);
            *reinterpret_cast<float4*>(b)     = *reinterpret_cast<float4*>(&Bs[k][tx * 8]);
            *reinterpret_cast<float4*>(b + 4) = *reinterpret_cast<float4*>(&Bs[k][tx * 8 + 4]);
            #pragma unroll
            for (int i = 0; i < 8; i++)
                #pragma unroll
                for (int j = 0; j < 8; j++)
                    c[i][j] = fmaf(a[i], b[j], c[i][j]);
        }
        __syncthreads();
    }

    #pragma unroll
    for (int i = 0; i < 8; i++) {
        const int row = m0 + ty * 8 + i;
        #pragma unroll
        for (int j = 0; j < 8; j += 4) {
            const int col = n0 + tx * 8 + j;
            float4 o;
            o.x = c[i][j + 0] + bias[col + 0];
            o.y = c[i][j + 1] + bias[col + 1];
            o.z = c[i][j + 2] + bias[col + 2];
            o.w = c[i][j + 3] + bias[col + 3];
            if (GELU) {
                o.x = gelu_tanh(o.x); o.y = gelu_tanh(o.y);
                o.z = gelu_tanh(o.z); o.w = gelu_tanh(o.w);
            }
            if (RES) {
                const float4 r = *reinterpret_cast<const float4*>(R + (size_t)row * N + col);
                o.x += r.x; o.y += r.y; o.z += r.z; o.w += r.w;
            }
            *reinterpret_cast<float4*>(C + (size_t)row * N + col) = o;
        }
    }
}

// ---------------- Flash attention (causal, 64x64 tiles, d=64) ----------------
#define FA_STRIDE 68  // padded row stride in floats (16B-aligned, conflict-reducing)

__global__ void __launch_bounds__(256) flash_attn_kernel(
    const float* __restrict__ qkv, float* __restrict__ ctx)
{
    const int qt = blockIdx.x, h = blockIdx.y, b = blockIdx.z;
    const int q0 = qt * 64;
    extern __shared__ float sm[];
    float* Qt = sm;                   // [d][q]   64 x 68
    float* Kt = sm + 64 * FA_STRIDE;  // [d][k]
    float* Vs = sm + 2 * 64 * FA_STRIDE;  // [k][d]
    float* Pt = sm + 3 * 64 * FA_STRIDE;  // [k][q]

    const int tid = threadIdx.x;
    const int tx = tid & 15, ty = tid >> 4;
    const int lrow = tid >> 2, lq = tid & 3;

    // Load Q tile transposed: Qt[d][row]
    {
        const float* qbase = qkv + ((size_t)(b * SEQ + q0) * 3) * 1024 + h * 64;
        #pragma unroll
        for (int r = 0; r < 4; r++) {
            const int d0 = (lq + r * 4) * 4;
            float4 v = *reinterpret_cast<const float4*>(qbase + (size_t)lrow * 3072 + d0);
            Qt[(d0 + 0) * FA_STRIDE + lrow] = v.x;
            Qt[(d0 + 1) * FA_STRIDE + lrow] = v.y;
            Qt[(d0 + 2) * FA_STRIDE + lrow] = v.z;
            Qt[(d0 + 3) * FA_STRIDE + lrow] = v.w;
        }
    }

    float m[4], l[4], o[4][4];
    #pragma unroll
    for (int i = 0; i < 4; i++) {
        m[i] = -1e30f; l[i] = 0.f;
        #pragma unroll
        for (int j = 0; j < 4; j++) o[i][j] = 0.f;
    }

    for (int kt = 0; kt <= qt; kt++) {
        const int k0 = kt * 64;
        __syncthreads();  // protect Kt/Vs/Pt from previous iteration's readers
        {
            const float* kbase = qkv + ((size_t)(b * SEQ + k0) * 3 + 1) * 1024 + h * 64;
            const float* vbase = qkv + ((size_t)(b * SEQ + k0) * 3 + 2) * 1024 + h * 64;
            #pragma unroll
            for (int r = 0; r < 4; r++) {
                const int d0 = (lq + r * 4) * 4;
                float4 kv = *reinterpret_cast<const float4*>(kbase + (size_t)lrow * 3072 + d0);
                Kt[(d0 + 0) * FA_STRIDE + lrow] = kv.x;
                Kt[(d0 + 1) * FA_STRIDE + lrow] = kv.y;
                Kt[(d0 + 2) * FA_STRIDE + lrow] = kv.z;
                Kt[(d0 + 3) * FA_STRIDE + lrow] = kv.w;
                float4 vv = *reinterpret_cast<const float4*>(vbase + (size_t)lrow * 3072 + d0);
                *reinterpret_cast<float4*>(&Vs[lrow * FA_STRIDE + d0]) = vv;
            }
        }
        __syncthreads();

        // S = Q K^T  (thread owns 4 rows x 4 cols of the 64x64 tile)
        float s[4][4];
        #pragma unroll
        for (int i = 0; i < 4; i++)
            #pragma unroll
            for (int j = 0; j < 4; j++) s[i][j] = 0.f;
        #pragma unroll 8
        for (int d = 0; d < 64; d++) {
            float4 qv = *reinterpret_cast<float4*>(&Qt[d * FA_STRIDE + ty * 4]);
            float4 kv = *reinterpret_cast<float4*>(&Kt[d * FA_STRIDE + tx * 4]);
            float qa[4] = {qv.x, qv.y, qv.z, qv.w};
            float ka[4] = {kv.x, kv.y, kv.z, kv.w};
            #pragma unroll
            for (int i = 0; i < 4; i++)
                #pragma unroll
                for (int j = 0; j < 4; j++)
                    s[i][j] = fmaf(qa[i], ka[j], s[i][j]);
        }

        // scale + causal mask (only diagonal tile needs masking)
        const float scale = 0.125f;  // 1/sqrt(64)
        #pragma unroll
        for (int i = 0; i < 4; i++)
            #pragma unroll
            for (int j = 0; j < 4; j++) {
                s[i][j] *= scale;
                if (kt == qt && (k0 + tx * 4 + j) > (q0 + ty * 4 + i)) s[i][j] = -1e30f;
            }

        // online softmax per row (reduce across the 16 tx lanes)
        #pragma unroll
        for (int i = 0; i < 4; i++) {
            float mx = fmaxf(fmaxf(s[i][0], s[i][1]), fmaxf(s[i][2], s[i][3]));
            #pragma unroll
            for (int off = 8; off; off >>= 1)
                mx = fmaxf(mx, __shfl_xor_sync(0xffffffffu, mx, off));
            const float mn = fmaxf(m[i], mx);
            const float alpha = __expf(m[i] - mn);
            float sum = 0.f;
            #pragma unroll
            for (int j = 0; j < 4; j++) {
                const float p = __expf(s[i][j] - mn);
                s[i][j] = p;
                sum += p;
            }
            #pragma unroll
            for (int off = 8; off; off >>= 1)
                sum += __shfl_xor_sync(0xffffffffu, sum, off);
            l[i] = l[i] * alpha + sum;
            m[i] = mn;
            #pragma unroll
            for (int j = 0; j < 4; j++) o[i][j] *= alpha;
        }

        // store P transposed: Pt[k][q]
        #pragma unroll
        for (int i = 0; i < 4; i++)
            #pragma unroll
            for (int j = 0; j < 4; j++)
                Pt[(tx * 4 + j) * FA_STRIDE + ty * 4 + i] = s[i][j];
        __syncthreads();

        // O += P @ V
        #pragma unroll 8
        for (int kk = 0; kk < 64; kk++) {
            float4 pv = *reinterpret_cast<float4*>(&Pt[kk * FA_STRIDE + ty * 4]);
            float4 vv = *reinterpret_cast<float4*>(&Vs[kk * FA_STRIDE + tx * 4]);
            float pa[4] = {pv.x, pv.y, pv.z, pv.w};
            float va[4] = {vv.x, vv.y, vv.z, vv.w};
            #pragma unroll
            for (int i = 0; i < 4; i++)
                #pragma unroll
                for (int j = 0; j < 4; j++)
                    o[i][j] = fmaf(pa[i], va[j], o[i][j]);
        }
    }

    // finalize + write ctx[b, s, h*64 + d]
    float* obase = ctx + (size_t)(b * SEQ + q0) * 1024 + h * 64;
    #pragma unroll
    for (int i = 0; i < 4; i++) {
        const float inv = 1.0f / l[i];
        float4 ov;
        ov.x = o[i][0] * inv; ov.y = o[i][1] * inv;
        ov.z = o[i][2] * inv; ov.w = o[i][3] * inv;
        *reinterpret_cast<float4*>(obase + (size_t)(ty * 4 + i) * 1024 + tx * 4) = ov;
    }
}

// ---------------- launch ----------------
extern "C" void kernel_launch(void* const* d_in, const int* in_sizes, int n_in,
                              void* d_out, int out_size)
{
    const float* x      = (const float*)d_in[0];
    const float* w_qkv  = (const float*)d_in[1];
    const float* b_qkv  = (const float*)d_in[2];
    const float* w_out  = (const float*)d_in[3];
    const float* b_out  = (const float*)d_in[4];
    const float* w_fc1  = (const float*)d_in[5];
    const float* b_fc1  = (const float*)d_in[6];
    const float* w_fc2  = (const float*)d_in[7];
    const float* b_fc2  = (const float*)d_in[8];
    const float* ln1s   = (const float*)d_in[9];
    const float* ln1b   = (const float*)d_in[10];
    const float* ln2s   = (const float*)d_in[11];
    const float* ln2b   = (const float*)d_in[12];
    float* out = (float*)d_out;

    float *p_ln, *p_qkv, *p_ctx, *p_x1, *p_h;
    cudaGetSymbolAddress((void**)&p_ln,  g_ln);
    cudaGetSymbolAddress((void**)&p_qkv, g_qkv);
    cudaGetSymbolAddress((void**)&p_ctx, g_ctx);
    cudaGetSymbolAddress((void**)&p_x1,  g_x1);
    cudaGetSymbolAddress((void**)&p_h,   g_h);

    const int flash_smem = 4 * 64 * FA_STRIDE * sizeof(float);  // 69632 B
    cudaFuncSetAttribute(flash_attn_kernel,
                         cudaFuncAttributeMaxDynamicSharedMemorySize, flash_smem);

    // 1) LN1
    ln_kernel<<<MROWS, 256>>>(x, ln1s, ln1b, p_ln);
    // 2) QKV projection: [8192,1024] @ [1024,3072]
    sgemm_kernel<false, false><<<dim3(3072 / 128, MROWS / 128), 256>>>(
        p_ln, w_qkv, b_qkv, nullptr, p_qkv, MROWS, 3072, 1024);
    // 3) causal flash attention
    flash_attn_kernel<<<dim3(SEQ / 64, NH, BATCH), 256, flash_smem>>>(p_qkv, p_ctx);
    // 4) output projection + residual(x)
    sgemm_kernel<false, true><<<dim3(1024 / 128, MROWS / 128), 256>>>(
        p_ctx, w_out, b_out, x, p_x1, MROWS, 1024, 1024);
    // 5) LN2
    ln_kernel<<<MROWS, 256>>>(p_x1, ln2s, ln2b, p_ln);
    // 6) FC1 + GELU
    sgemm_kernel<true, false><<<dim3(DFF / 128, MROWS / 128), 256>>>(
        p_ln, w_fc1, b_fc1, nullptr, p_h, MROWS, DFF, 1024);
    // 7) FC2 + residual(x1) -> out
    sgemm_kernel<false, true><<<dim3(1024 / 128, MROWS / 128), 256>>>(
        p_h, w_fc2, b_fc2, p_x1, out, MROWS, 1024, DFF);
}

// round 3
// speedup vs baseline: 1.8399x; 1.8399x over previous
#include <cuda_runtime.h>
#include <cuda_bf16.h>
#include <math.h>
#include <stdint.h>

#define D_MODEL 1024
#define SEQ     2048
#define BATCH   4
#define NH      16
#define DFF     4096
#define MROWS   (BATCH*SEQ)   /* 8192 */

// ---------------- scratch (device globals: allocation-free) ----------------
__device__ float          g_qkv [MROWS * 3 * D_MODEL];
__device__ float          g_ctx [MROWS * D_MODEL];
__device__ float          g_x1  [MROWS * D_MODEL];
__device__ __nv_bfloat16  g_lnh [MROWS * D_MODEL];
__device__ __nv_bfloat16  g_lnl [MROWS * D_MODEL];
__device__ __nv_bfloat16  g_ctxh[MROWS * D_MODEL];
__device__ __nv_bfloat16  g_ctxl[MROWS * D_MODEL];
__device__ __nv_bfloat16  g_hh  [MROWS * DFF];
__device__ __nv_bfloat16  g_hl  [MROWS * DFF];
// transposed+split weights: [N][K]
__device__ __nv_bfloat16  g_wqh [3 * D_MODEL * D_MODEL];
__device__ __nv_bfloat16  g_wql [3 * D_MODEL * D_MODEL];
__device__ __nv_bfloat16  g_woh [D_MODEL * D_MODEL];
__device__ __nv_bfloat16  g_wol [D_MODEL * D_MODEL];
__device__ __nv_bfloat16  g_w1h [DFF * D_MODEL];
__device__ __nv_bfloat16  g_w1l [DFF * D_MODEL];
__device__ __nv_bfloat16  g_w2h [D_MODEL * DFF];
__device__ __nv_bfloat16  g_w2l [D_MODEL * DFF];

// ---------------- PTX helpers (baseline-PTX only: no tcgen05) ----------------
__device__ __forceinline__ uint32_t smem_u32(const void* p) {
    return (uint32_t)__cvta_generic_to_shared(p);
}
__device__ __forceinline__ void cpa16(uint32_t dst, const void* src) {
    asm volatile("cp.async.cg.shared.global [%0], [%1], 16;" :: "r"(dst), "l"(src));
}
__device__ __forceinline__ void cp_commit() { asm volatile("cp.async.commit_group;" ::: "memory"); }
__device__ __forceinline__ void cp_wait1()  { asm volatile("cp.async.wait_group 1;"  ::: "memory"); }
__device__ __forceinline__ void cp_wait0()  { asm volatile("cp.async.wait_group 0;"  ::: "memory"); }

__device__ __forceinline__ void ldsm_x4(uint32_t& r0, uint32_t& r1, uint32_t& r2, uint32_t& r3,
                                        uint32_t addr) {
    asm volatile("ldmatrix.sync.aligned.m8n8.x4.shared.b16 {%0,%1,%2,%3}, [%4];"
                 : "=r"(r0), "=r"(r1), "=r"(r2), "=r"(r3) : "r"(addr));
}
__device__ __forceinline__ void mma16816(float* c, uint32_t a0, uint32_t a1, uint32_t a2,
                                         uint32_t a3, uint32_t b0, uint32_t b1) {
    asm volatile("mma.sync.aligned.m16n8k16.row.col.f32.bf16.bf16.f32 "
                 "{%0,%1,%2,%3}, {%4,%5,%6,%7}, {%8,%9}, {%0,%1,%2,%3};"
                 : "+f"(c[0]), "+f"(c[1]), "+f"(c[2]), "+f"(c[3])
                 : "r"(a0), "r"(a1), "r"(a2), "r"(a3), "r"(b0), "r"(b1));
}

// ---------------- misc math ----------------
__device__ __forceinline__ float gelu_tanh(float x) {
    float x3 = x * x * x;
    return 0.5f * x * (1.0f + tanhf(0.7978845608028654f * (x + 0.044715f * x3)));
}
__device__ __forceinline__ void split_bf16(float v, __nv_bfloat16& h, __nv_bfloat16& l) {
    h = __float2bfloat16(v);
    l = __float2bfloat16(v - __bfloat162float(h));
}

// ================= LayerNorm -> bf16 hi/lo pair =================
__device__ __forceinline__ float block_reduce_sum(float v, float* sbuf) {
    int lane = threadIdx.x & 31, wid = threadIdx.x >> 5;
    #pragma unroll
    for (int o = 16; o; o >>= 1) v += __shfl_xor_sync(0xffffffffu, v, o);
    if (lane == 0) sbuf[wid] = v;
    __syncthreads();
    if (wid == 0) {
        float r = (lane < 8) ? sbuf[lane] : 0.f;
        #pragma unroll
        for (int o = 4; o; o >>= 1) r += __shfl_xor_sync(0xffffffffu, r, o);
        if (lane == 0) sbuf[8] = r;
    }
    __syncthreads();
    float out = sbuf[8];
    __syncthreads();
    return out;
}

__global__ void __launch_bounds__(256) ln_kernel(
    const float* __restrict__ x, const float* __restrict__ sc,
    const float* __restrict__ bi,
    __nv_bfloat16* __restrict__ yh, __nv_bfloat16* __restrict__ yl)
{
    __shared__ float red[9];
    int row = blockIdx.x;
    int t = threadIdx.x;
    const float4 v = *reinterpret_cast<const float4*>(x + (size_t)row * D_MODEL + t * 4);
    float s = v.x + v.y + v.z + v.w;
    s = block_reduce_sum(s, red);
    float mu = s * (1.0f / D_MODEL);
    float d0 = v.x - mu, d1 = v.y - mu, d2 = v.z - mu, d3 = v.w - mu;
    float sq = d0*d0 + d1*d1 + d2*d2 + d3*d3;
    sq = block_reduce_sum(sq, red);
    float inv = rsqrtf(sq * (1.0f / D_MODEL) + 1e-6f);
    const float4 scv = *reinterpret_cast<const float4*>(sc + t * 4);
    const float4 biv = *reinterpret_cast<const float4*>(bi + t * 4);
    float o0 = d0 * inv * scv.x + biv.x;
    float o1 = d1 * inv * scv.y + biv.y;
    float o2 = d2 * inv * scv.z + biv.z;
    float o3 = d3 * inv * scv.w + biv.w;
    __nv_bfloat16 h0, l0, h1, l1, h2, l2, h3, l3;
    split_bf16(o0, h0, l0); split_bf16(o1, h1, l1);
    split_bf16(o2, h2, l2); split_bf16(o3, h3, l3);
    size_t off = (size_t)row * D_MODEL + t * 4;
    *reinterpret_cast<__nv_bfloat162*>(yh + off)     = __nv_bfloat162(h0, h1);
    *reinterpret_cast<__nv_bfloat162*>(yh + off + 2) = __nv_bfloat162(h2, h3);
    *reinterpret_cast<__nv_bfloat162*>(yl + off)     = __nv_bfloat162(l0, l1);
    *reinterpret_cast<__nv_bfloat162*>(yl + off + 2) = __nv_bfloat162(l2, l3);
}

// ================= fp32 -> bf16 hi/lo split =================
__global__ void __launch_bounds__(256) split_kernel(
    const float* __restrict__ in, __nv_bfloat16* __restrict__ oh,
    __nv_bfloat16* __restrict__ ol, int n4)
{
    int i = blockIdx.x * blockDim.x + threadIdx.x;
    if (i >= n4) return;
    float4 v = reinterpret_cast<const float4*>(in)[i];
    __nv_bfloat16 h0, l0, h1, l1, h2, l2, h3, l3;
    split_bf16(v.x, h0, l0); split_bf16(v.y, h1, l1);
    split_bf16(v.z, h2, l2); split_bf16(v.w, h3, l3);
    size_t off = (size_t)i * 4;
    *reinterpret_cast<__nv_bfloat162*>(oh + off)     = __nv_bfloat162(h0, h1);
    *reinterpret_cast<__nv_bfloat162*>(oh + off + 2) = __nv_bfloat162(h2, h3);
    *reinterpret_cast<__nv_bfloat162*>(ol + off)     = __nv_bfloat162(l0, l1);
    *reinterpret_cast<__nv_bfloat162*>(ol + off + 2) = __nv_bfloat162(l2, l3);
}

// ================= weight transpose + split: w[K][N] -> t[N][K] hi/lo =================
__global__ void __launch_bounds__(256) transpose_split(
    const float* __restrict__ w, __nv_bfloat16* __restrict__ th,
    __nv_bfloat16* __restrict__ tl, int K, int N)
{
    __shared__ float tile[32][33];
    int k0 = blockIdx.x * 32, n0 = blockIdx.y * 32;
    int tx = threadIdx.x, ty = threadIdx.y;   // (32, 8)
    #pragma unroll
    for (int i = 0; i < 32; i += 8)
        tile[ty + i][tx] = w[(size_t)(k0 + ty + i) * N + n0 + tx];
    __syncthreads();
    #pragma unroll
    for (int i = 0; i < 32; i += 8) {
        float v = tile[tx][ty + i];
        __nv_bfloat16 h, l;
        split_bf16(v, h, l);
        th[(size_t)(n0 + ty + i) * K + k0 + tx] = h;
        tl[(size_t)(n0 + ty + i) * K + k0 + tx] = l;
    }
}

// ================= split-bf16 GEMM via mma.sync (HMMA) =================
// C[M,N] = A[M,K] @ Bt[N,K]^T (+bias)(+gelu)(+res); fp32 accum; 3-MMA split.
// CTA 128x128, 8 warps (2x4), warp tile 64x32, KC=32, 3-stage cp.async.
#define KC 32
#define APAD 40                 /* bf16 elements per smem row (32 + 8 pad) => 80B */
#define TILE_BYTES (128 * APAD * 2)   /* 10240 */
#define OFF_AH 0
#define OFF_AL (TILE_BYTES)
#define OFF_BH (2 * TILE_BYTES)
#define OFF_BL (3 * TILE_BYTES)
#define STAGE_BYTES (4 * TILE_BYTES)  /* 40960 */
#define NSTAGE 3
#define GEMM_SMEM (NSTAGE * STAGE_BYTES)

__device__ __forceinline__ void load_chunk(
    uint32_t sbase,
    const __nv_bfloat16* __restrict__ Ah, const __nv_bfloat16* __restrict__ Al,
    const __nv_bfloat16* __restrict__ Bh, const __nv_bfloat16* __restrict__ Bl,
    int m0, int n0, int K, int k0, int tid)
{
    // each tile: 128 rows x 4 x 16B segs = 512 cpa16; 256 threads -> 2 each
    #pragma unroll
    for (int j = 0; j < 2; j++) {
        int idx = tid + j * 256;
        int r = idx >> 2, sg = idx & 3;
        uint32_t d = (uint32_t)(r * (APAD * 2) + sg * 16);
        size_t ga = (size_t)(m0 + r) * K + k0 + sg * 8;
        size_t gb = (size_t)(n0 + r) * K + k0 + sg * 8;
        cpa16(sbase + OFF_AH + d, Ah + ga);
        cpa16(sbase + OFF_AL + d, Al + ga);
        cpa16(sbase + OFF_BH + d, Bh + gb);
        cpa16(sbase + OFF_BL + d, Bl + gb);
    }
}

template<bool GELU_, bool RES_, bool BF16OUT>
__global__ void __launch_bounds__(256) gemm_mma(
    const __nv_bfloat16* __restrict__ Ah, const __nv_bfloat16* __restrict__ Al,
    const __nv_bfloat16* __restrict__ Bh, const __nv_bfloat16* __restrict__ Bl,
    const float* __restrict__ bias, const float* __restrict__ Res,
    float* __restrict__ Cf, __nv_bfloat16* __restrict__ Ch, __nv_bfloat16* __restrict__ Cl,
    int M, int N, int K)
{
    extern __shared__ char smem[];
    const uint32_t sb = smem_u32(smem);
    const int tid = threadIdx.x;
    const int wid = tid >> 5, lane = tid & 31;
    const int m0 = blockIdx.y * 128, n0 = blockIdx.x * 128;
    const int wm = (wid >> 2) * 64;   // warp m offset (0 / 64)
    const int wn = (wid & 3) * 32;    // warp n offset

    // ldmatrix lane address components
    const int a_r = lane & 15;
    const int a_c = (lane & 16) ? 8 : 0;
    const int b_r = (lane & 7) + ((lane & 16) ? 8 : 0);
    const int b_c = (lane & 8) ? 8 : 0;

    float c[4][4][4];
    #pragma unroll
    for (int i = 0; i < 4; i++)
        #pragma unroll
        for (int j = 0; j < 4; j++)
            #pragma unroll
            for (int e = 0; e < 4; e++) c[i][j][e] = 0.f;

    // prologue
    load_chunk(sb, Ah, Al, Bh, Bl, m0, n0, K, 0, tid);
    cp_commit();
    load_chunk(sb + STAGE_BYTES, Ah, Al, Bh, Bl, m0, n0, K, KC, tid);
    cp_commit();

    const int NC = K / KC;
    int stage = 0;
    for (int i = 0; i < NC; i++) {
        if (i + 2 < NC) cp_wait1(); else cp_wait0();
        __syncthreads();
        if (i + 2 < NC) {
            int ls = stage + 2; if (ls >= NSTAGE) ls -= NSTAGE;
            load_chunk(sb + ls * STAGE_BYTES, Ah, Al, Bh, Bl, m0, n0, K, (i + 2) * KC, tid);
            cp_commit();
        }
        const uint32_t st = sb + stage * STAGE_BYTES;
        const uint32_t aA = st + (wm + a_r) * (APAD * 2) + a_c * 2;
        const uint32_t aB = st + (wn + b_r) * (APAD * 2) + b_c * 2;
        #pragma unroll
        for (int kk = 0; kk < KC; kk += 16) {
            uint32_t ah[4][4], al[4][4], bh[2][4], bl[2][4];
            #pragma unroll
            for (int mt = 0; mt < 4; mt++) {
                uint32_t ad = aA + mt * 16 * (APAD * 2) + kk * 2;
                ldsm_x4(ah[mt][0], ah[mt][1], ah[mt][2], ah[mt][3], ad + OFF_AH);
                ldsm_x4(al[mt][0], al[mt][1], al[mt][2], al[mt][3], ad + OFF_AL);
            }
            #pragma unroll
            for (int g = 0; g < 2; g++) {
                uint32_t bd = aB + g * 16 * (APAD * 2) + kk * 2;
                ldsm_x4(bh[g][0], bh[g][1], bh[g][2], bh[g][3], bd + OFF_BH);
                ldsm_x4(bl[g][0], bl[g][1], bl[g][2], bl[g][3], bd + OFF_BL);
            }
            #pragma unroll
            for (int mt = 0; mt < 4; mt++)
                #pragma unroll
                for (int nt = 0; nt < 4; nt++) {
                    const int g = nt >> 1, h = (nt & 1) * 2;
                    mma16816(c[mt][nt], ah[mt][0], ah[mt][1], ah[mt][2], ah[mt][3],
                             bh[g][h], bh[g][h + 1]);
                    mma16816(c[mt][nt], ah[mt][0], ah[mt][1], ah[mt][2], ah[mt][3],
                             bl[g][h], bl[g][h + 1]);
                    mma16816(c[mt][nt], al[mt][0], al[mt][1], al[mt][2], al[mt][3],
                             bh[g][h], bh[g][h + 1]);
                }
        }
        stage++; if (stage >= NSTAGE) stage = 0;
    }

    // epilogue straight from fragments
    const int t4 = lane >> 2, cp = (lane & 3) * 2;
    #pragma unroll
    for (int mt = 0; mt < 4; mt++) {
        #pragma unroll
        for (int half = 0; half < 2; half++) {
            const int row = m0 + wm + mt * 16 + t4 + half * 8;
            #pragma unroll
            for (int nt = 0; nt < 4; nt++) {
                const int col = n0 + wn + nt * 8 + cp;
                float v0 = c[mt][nt][half * 2 + 0];
                float v1 = c[mt][nt][half * 2 + 1];
                const float2 bv = *reinterpret_cast<const float2*>(bias + col);
                v0 += bv.x; v1 += bv.y;
                if (GELU_) { v0 = gelu_tanh(v0); v1 = gelu_tanh(v1); }
                if (RES_) {
                    const float2 rv = *reinterpret_cast<const float2*>(
                        Res + (size_t)row * N + col);
                    v0 += rv.x; v1 += rv.y;
                }
                const size_t oof = (size_t)row * N + col;
                if (BF16OUT) {
                    __nv_bfloat16 h0, l0, h1, l1;
                    split_bf16(v0, h0, l0); split_bf16(v1, h1, l1);
                    *reinterpret_cast<__nv_bfloat162*>(Ch + oof) = __nv_bfloat162(h0, h1);
                    *reinterpret_cast<__nv_bfloat162*>(Cl + oof) = __nv_bfloat162(l0, l1);
                } else {
                    float2 ov; ov.x = v0; ov.y = v1;
                    *reinterpret_cast<float2*>(Cf + oof) = ov;
                }
            }
        }
    }
}

// ================= Flash attention (fp32) =================
#define FA_STRIDE 68

__global__ void __launch_bounds__(256) flash_attn_kernel(
    const float* __restrict__ qkv, float* __restrict__ ctx)
{
    const int qt = blockIdx.x, h = blockIdx.y, b = blockIdx.z;
    const int q0 = qt * 64;
    extern __shared__ float sm[];
    float* Qt = sm;
    float* Kt = sm + 64 * FA_STRIDE;
    float* Vs = sm + 2 * 64 * FA_STRIDE;
    float* Pt = sm + 3 * 64 * FA_STRIDE;

    const int tid = threadIdx.x;
    const int tx = tid & 15, ty = tid >> 4;
    const int lrow = tid >> 2, lq = tid & 3;

    {
        const float* qbase = qkv + ((size_t)(b * SEQ + q0) * 3) * 1024 + h * 64;
        #pragma unroll
        for (int r = 0; r < 4; r++) {
            const int d0 = (lq + r * 4) * 4;
            float4 v = *reinterpret_cast<const float4*>(qbase + (size_t)lrow * 3072 + d0);
            Qt[(d0 + 0) * FA_STRIDE + lrow] = v.x;
            Qt[(d0 + 1) * FA_STRIDE + lrow] = v.y;
            Qt[(d0 + 2) * FA_STRIDE + lrow] = v.z;
            Qt[(d0 + 3) * FA_STRIDE + lrow] = v.w;
        }
    }

    float m[4], l[4], o[4][4];
    #pragma unroll
    for (int i = 0; i < 4; i++) {
        m[i] = -1e30f; l[i] = 0.f;
        #pragma unroll
        for (int j = 0; j < 4; j++) o[i][j] = 0.f;
    }

    for (int kt = 0; kt <= qt; kt++) {
        const int k0 = kt * 64;
        __syncthreads();
        {
            const float* kbase = qkv + ((size_t)(b * SEQ + k0) * 3 + 1) * 1024 + h * 64;
            const float* vbase = qkv + ((size_t)(b * SEQ + k0) * 3 + 2) * 1024 + h * 64;
            #pragma unroll
            for (int r = 0; r < 4; r++) {
                const int d0 = (lq + r * 4) * 4;
                float4 kv = *reinterpret_cast<const float4*>(kbase + (size_t)lrow * 3072 + d0);
                Kt[(d0 + 0) * FA_STRIDE + lrow] = kv.x;
                Kt[(d0 + 1) * FA_STRIDE + lrow] = kv.y;
                Kt[(d0 + 2) * FA_STRIDE + lrow] = kv.z;
                Kt[(d0 + 3) * FA_STRIDE + lrow] = kv.w;
                float4 vv = *reinterpret_cast<const float4*>(vbase + (size_t)lrow * 3072 + d0);
                *reinterpret_cast<float4*>(&Vs[lrow * FA_STRIDE + d0]) = vv;
            }
        }
        __syncthreads();

        float s[4][4];
        #pragma unroll
        for (int i = 0; i < 4; i++)
            #pragma unroll
            for (int j = 0; j < 4; j++) s[i][j] = 0.f;
        #pragma unroll 8
        for (int d = 0; d < 64; d++) {
            float4 qv = *reinterpret_cast<float4*>(&Qt[d * FA_STRIDE + ty * 4]);
            float4 kv = *reinterpret_cast<float4*>(&Kt[d * FA_STRIDE + tx * 4]);
            float qa[4] = {qv.x, qv.y, qv.z, qv.w};
            float ka[4] = {kv.x, kv.y, kv.z, kv.w};
            #pragma unroll
            for (int i = 0; i < 4; i++)
                #pragma unroll
                for (int j = 0; j < 4; j++)
                    s[i][j] = fmaf(qa[i], ka[j], s[i][j]);
        }

        const float scale = 0.125f;
        #pragma unroll
        for (int i = 0; i < 4; i++)
            #pragma unroll
            for (int j = 0; j < 4; j++) {
                s[i][j] *= scale;
                if (kt == qt && (k0 + tx * 4 + j) > (q0 + ty * 4 + i)) s[i][j] = -1e30f;
            }

        #pragma unroll
        for (int i = 0; i < 4; i++) {
            float mx = fmaxf(fmaxf(s[i][0], s[i][1]), fmaxf(s[i][2], s[i][3]));
            #pragma unroll
            for (int off = 8; off; off >>= 1)
                mx = fmaxf(mx, __shfl_xor_sync(0xffffffffu, mx, off));
            const float mn = fmaxf(m[i], mx);
            const float alpha = __expf(m[i] - mn);
            float sum = 0.f;
            #pragma unroll
            for (int j = 0; j < 4; j++) {
                const float p = __expf(s[i][j] - mn);
                s[i][j] = p;
                sum += p;
            }
            #pragma unroll
            for (int off = 8; off; off >>= 1)
                sum += __shfl_xor_sync(0xffffffffu, sum, off);
            l[i] = l[i] * alpha + sum;
            m[i] = mn;
            #pragma unroll
            for (int j = 0; j < 4; j++) o[i][j] *= alpha;
        }

        #pragma unroll
        for (int i = 0; i < 4; i++)
            #pragma unroll
            for (int j = 0; j < 4; j++)
                Pt[(tx * 4 + j) * FA_STRIDE + ty * 4 + i] = s[i][j];
        __syncthreads();

        #pragma unroll 8
        for (int kk = 0; kk < 64; kk++) {
            float4 pv = *reinterpret_cast<float4*>(&Pt[kk * FA_STRIDE + ty * 4]);
            float4 vv = *reinterpret_cast<float4*>(&Vs[kk * FA_STRIDE + tx * 4]);
            float pa[4] = {pv.x, pv.y, pv.z, pv.w};
            float va[4] = {vv.x, vv.y, vv.z, vv.w};
            #pragma unroll
            for (int i = 0; i < 4; i++)
                #pragma unroll
                for (int j = 0; j < 4; j++)
                    o[i][j] = fmaf(pa[i], va[j], o[i][j]);
        }
    }

    float* obase = ctx + (size_t)(b * SEQ + q0) * 1024 + h * 64;
    #pragma unroll
    for (int i = 0; i < 4; i++) {
        const float inv = 1.0f / l[i];
        float4 ov;
        ov.x = o[i][0] * inv; ov.y = o[i][1] * inv;
        ov.z = o[i][2] * inv; ov.w = o[i][3] * inv;
        *reinterpret_cast<float4*>(obase + (size_t)(ty * 4 + i) * 1024 + tx * 4) = ov;
    }
}

// ================= launch =================
extern "C" void kernel_launch(void* const* d_in, const int* in_sizes, int n_in,
                              void* d_out, int out_size)
{
    const float* x      = (const float*)d_in[0];
    const float* w_qkv  = (const float*)d_in[1];
    const float* b_qkv  = (const float*)d_in[2];
    const float* w_out  = (const float*)d_in[3];
    const float* b_out  = (const float*)d_in[4];
    const float* w_fc1  = (const float*)d_in[5];
    const float* b_fc1  = (const float*)d_in[6];
    const float* w_fc2  = (const float*)d_in[7];
    const float* b_fc2  = (const float*)d_in[8];
    const float* ln1s   = (const float*)d_in[9];
    const float* ln1b   = (const float*)d_in[10];
    const float* ln2s   = (const float*)d_in[11];
    const float* ln2b   = (const float*)d_in[12];
    float* out = (float*)d_out;

    float *p_qkv, *p_ctx, *p_x1;
    __nv_bfloat16 *p_lnh, *p_lnl, *p_ctxh, *p_ctxl, *p_hh, *p_hl;
    __nv_bfloat16 *p_wqh, *p_wql, *p_woh, *p_wol, *p_w1h, *p_w1l, *p_w2h, *p_w2l;
    cudaGetSymbolAddress((void**)&p_qkv,  g_qkv);
    cudaGetSymbolAddress((void**)&p_ctx,  g_ctx);
    cudaGetSymbolAddress((void**)&p_x1,   g_x1);
    cudaGetSymbolAddress((void**)&p_lnh,  g_lnh);
    cudaGetSymbolAddress((void**)&p_lnl,  g_lnl);
    cudaGetSymbolAddress((void**)&p_ctxh, g_ctxh);
    cudaGetSymbolAddress((void**)&p_ctxl, g_ctxl);
    cudaGetSymbolAddress((void**)&p_hh,   g_hh);
    cudaGetSymbolAddress((void**)&p_hl,   g_hl);
    cudaGetSymbolAddress((void**)&p_wqh,  g_wqh);
    cudaGetSymbolAddress((void**)&p_wql,  g_wql);
    cudaGetSymbolAddress((void**)&p_woh,  g_woh);
    cudaGetSymbolAddress((void**)&p_wol,  g_wol);
    cudaGetSymbolAddress((void**)&p_w1h,  g_w1h);
    cudaGetSymbolAddress((void**)&p_w1l,  g_w1l);
    cudaGetSymbolAddress((void**)&p_w2h,  g_w2h);
    cudaGetSymbolAddress((void**)&p_w2l,  g_w2l);

    cudaFuncSetAttribute(gemm_mma<false, false, false>,
                         cudaFuncAttributeMaxDynamicSharedMemorySize, GEMM_SMEM);
    cudaFuncSetAttribute(gemm_mma<false, true, false>,
                         cudaFuncAttributeMaxDynamicSharedMemorySize, GEMM_SMEM);
    cudaFuncSetAttribute(gemm_mma<true, false, true>,
                         cudaFuncAttributeMaxDynamicSharedMemorySize, GEMM_SMEM);
    const int flash_smem = 4 * 64 * FA_STRIDE * sizeof(float);
    cudaFuncSetAttribute(flash_attn_kernel,
                         cudaFuncAttributeMaxDynamicSharedMemorySize, flash_smem);

    dim3 tb32(32, 8);
    transpose_split<<<dim3(1024 / 32, 3072 / 32), tb32>>>(w_qkv, p_wqh, p_wql, 1024, 3072);
    transpose_split<<<dim3(1024 / 32, 1024 / 32), tb32>>>(w_out, p_woh, p_wol, 1024, 1024);
    transpose_split<<<dim3(1024 / 32, 4096 / 32), tb32>>>(w_fc1, p_w1h, p_w1l, 1024, 4096);
    transpose_split<<<dim3(4096 / 32, 1024 / 32), tb32>>>(w_fc2, p_w2h, p_w2l, 4096, 1024);

    // 1) LN1 -> bf16 pair
    ln_kernel<<<MROWS, 256>>>(x, ln1s, ln1b, p_lnh, p_lnl);
    // 2) QKV projection (fp32 out)
    gemm_mma<false, false, false><<<dim3(3072 / 128, MROWS / 128), 256, GEMM_SMEM>>>(
        p_lnh, p_lnl, p_wqh, p_wql, b_qkv, nullptr, p_qkv, nullptr, nullptr,
        MROWS, 3072, 1024);
    // 3) flash attention
    flash_attn_kernel<<<dim3(SEQ / 64, NH, BATCH), 256, flash_smem>>>(p_qkv, p_ctx);
    // 4) ctx -> bf16 pair
    split_kernel<<<(MROWS * D_MODEL / 4 + 255) / 256, 256>>>(p_ctx, p_ctxh, p_ctxl,
                                                             MROWS * D_MODEL / 4);
    // 5) out projection + residual(x)
    gemm_mma<false, true, false><<<dim3(1024 / 128, MROWS / 128), 256, GEMM_SMEM>>>(
        p_ctxh, p_ctxl, p_woh, p_wol, b_out, x, p_x1, nullptr, nullptr,
        MROWS, 1024, 1024);
    // 6) LN2 -> bf16 pair
    ln_kernel<<<MROWS, 256>>>(p_x1, ln2s, ln2b, p_lnh, p_lnl);
    // 7) FC1 + GELU -> bf16 pair
    gemm_mma<true, false, true><<<dim3(4096 / 128, MROWS / 128), 256, GEMM_SMEM>>>(
        p_lnh, p_lnl, p_w1h, p_w1l, b_fc1, nullptr, nullptr, p_hh, p_hl,
        MROWS, 4096, 1024);
    // 8) FC2 + residual(x1) -> out
    gemm_mma<false, true, false><<<dim3(1024 / 128, MROWS / 128), 256, GEMM_SMEM>>>(
        p_hh, p_hl, p_w2h, p_w2l, b_fc2, p_x1, out, nullptr, nullptr,
        MROWS, 1024, 4096);
}

// round 4
// speedup vs baseline: 1.9336x; 1.0509x over previous
#include <cuda_runtime.h>
#include <cuda_bf16.h>
#include <math.h>
#include <stdint.h>

#define D_MODEL 1024
#define SEQ     2048
#define BATCH   4
#define NH      16
#define DFF     4096
#define MROWS   (BATCH*SEQ)   /* 8192 */

// ---------------- scratch (device globals: allocation-free) ----------------
__device__ float          g_qkv [MROWS * 3 * D_MODEL];
__device__ float          g_x1  [MROWS * D_MODEL];
__device__ __nv_bfloat16  g_lnh [MROWS * D_MODEL];
__device__ __nv_bfloat16  g_lnl [MROWS * D_MODEL];
__device__ __nv_bfloat16  g_ctxh[MROWS * D_MODEL];
__device__ __nv_bfloat16  g_ctxl[MROWS * D_MODEL];
__device__ __nv_bfloat16  g_hh  [MROWS * DFF];
__device__ __nv_bfloat16  g_hl  [MROWS * DFF];
// transposed+split weights: [N][K]
__device__ __nv_bfloat16  g_wqh [3 * D_MODEL * D_MODEL];
__device__ __nv_bfloat16  g_wql [3 * D_MODEL * D_MODEL];
__device__ __nv_bfloat16  g_woh [D_MODEL * D_MODEL];
__device__ __nv_bfloat16  g_wol [D_MODEL * D_MODEL];
__device__ __nv_bfloat16  g_w1h [DFF * D_MODEL];
__device__ __nv_bfloat16  g_w1l [DFF * D_MODEL];
__device__ __nv_bfloat16  g_w2h [D_MODEL * DFF];
__device__ __nv_bfloat16  g_w2l [D_MODEL * DFF];

// ---------------- PTX helpers (baseline-PTX only: no tcgen05) ----------------
__device__ __forceinline__ uint32_t smem_u32(const void* p) {
    return (uint32_t)__cvta_generic_to_shared(p);
}
__device__ __forceinline__ void cpa16(uint32_t dst, const void* src) {
    asm volatile("cp.async.cg.shared.global [%0], [%1], 16;" :: "r"(dst), "l"(src));
}
__device__ __forceinline__ void cp_commit() { asm volatile("cp.async.commit_group;" ::: "memory"); }
__device__ __forceinline__ void cp_wait1()  { asm volatile("cp.async.wait_group 1;"  ::: "memory"); }
__device__ __forceinline__ void cp_wait0()  { asm volatile("cp.async.wait_group 0;"  ::: "memory"); }

__device__ __forceinline__ void ldsm_x4(uint32_t& r0, uint32_t& r1, uint32_t& r2, uint32_t& r3,
                                        uint32_t addr) {
    asm volatile("ldmatrix.sync.aligned.m8n8.x4.shared.b16 {%0,%1,%2,%3}, [%4];"
                 : "=r"(r0), "=r"(r1), "=r"(r2), "=r"(r3) : "r"(addr));
}
__device__ __forceinline__ void mma16816(float* c, uint32_t a0, uint32_t a1, uint32_t a2,
                                         uint32_t a3, uint32_t b0, uint32_t b1) {
    asm volatile("mma.sync.aligned.m16n8k16.row.col.f32.bf16.bf16.f32 "
                 "{%0,%1,%2,%3}, {%4,%5,%6,%7}, {%8,%9}, {%0,%1,%2,%3};"
                 : "+f"(c[0]), "+f"(c[1]), "+f"(c[2]), "+f"(c[3])
                 : "r"(a0), "r"(a1), "r"(a2), "r"(a3), "r"(b0), "r"(b1));
}

// ---------------- misc math ----------------
__device__ __forceinline__ float gelu_tanh(float x) {
    float x3 = x * x * x;
    return 0.5f * x * (1.0f + tanhf(0.7978845608028654f * (x + 0.044715f * x3)));
}
__device__ __forceinline__ void split_bf16(float v, __nv_bfloat16& h, __nv_bfloat16& l) {
    h = __float2bfloat16(v);
    l = __float2bfloat16(v - __bfloat162float(h));
}

// ================= LayerNorm -> bf16 hi/lo pair =================
__device__ __forceinline__ float block_reduce_sum(float v, float* sbuf) {
    int lane = threadIdx.x & 31, wid = threadIdx.x >> 5;
    #pragma unroll
    for (int o = 16; o; o >>= 1) v += __shfl_xor_sync(0xffffffffu, v, o);
    if (lane == 0) sbuf[wid] = v;
    __syncthreads();
    if (wid == 0) {
        float r = (lane < 8) ? sbuf[lane] : 0.f;
        #pragma unroll
        for (int o = 4; o; o >>= 1) r += __shfl_xor_sync(0xffffffffu, r, o);
        if (lane == 0) sbuf[8] = r;
    }
    __syncthreads();
    float out = sbuf[8];
    __syncthreads();
    return out;
}

__global__ void __launch_bounds__(256) ln_kernel(
    const float* __restrict__ x, const float* __restrict__ sc,
    const float* __restrict__ bi,
    __nv_bfloat16* __restrict__ yh, __nv_bfloat16* __restrict__ yl)
{
    __shared__ float red[9];
    int row = blockIdx.x;
    int t = threadIdx.x;
    const float4 v = *reinterpret_cast<const float4*>(x + (size_t)row * D_MODEL + t * 4);
    float s = v.x + v.y + v.z + v.w;
    s = block_reduce_sum(s, red);
    float mu = s * (1.0f / D_MODEL);
    float d0 = v.x - mu, d1 = v.y - mu, d2 = v.z - mu, d3 = v.w - mu;
    float sq = d0*d0 + d1*d1 + d2*d2 + d3*d3;
    sq = block_reduce_sum(sq, red);
    float inv = rsqrtf(sq * (1.0f / D_MODEL) + 1e-6f);
    const float4 scv = *reinterpret_cast<const float4*>(sc + t * 4);
    const float4 biv = *reinterpret_cast<const float4*>(bi + t * 4);
    float o0 = d0 * inv * scv.x + biv.x;
    float o1 = d1 * inv * scv.y + biv.y;
    float o2 = d2 * inv * scv.z + biv.z;
    float o3 = d3 * inv * scv.w + biv.w;
    __nv_bfloat16 h0, l0, h1, l1, h2, l2, h3, l3;
    split_bf16(o0, h0, l0); split_bf16(o1, h1, l1);
    split_bf16(o2, h2, l2); split_bf16(o3, h3, l3);
    size_t off = (size_t)row * D_MODEL + t * 4;
    *reinterpret_cast<__nv_bfloat162*>(yh + off)     = __nv_bfloat162(h0, h1);
    *reinterpret_cast<__nv_bfloat162*>(yh + off + 2) = __nv_bfloat162(h2, h3);
    *reinterpret_cast<__nv_bfloat162*>(yl + off)     = __nv_bfloat162(l0, l1);
    *reinterpret_cast<__nv_bfloat162*>(yl + off + 2) = __nv_bfloat162(l2, l3);
}

// ================= weight transpose + split: w[K][N] -> t[N][K] hi/lo =================
__global__ void __launch_bounds__(256) transpose_split(
    const float* __restrict__ w, __nv_bfloat16* __restrict__ th,
    __nv_bfloat16* __restrict__ tl, int K, int N)
{
    __shared__ float tile[32][33];
    int k0 = blockIdx.x * 32, n0 = blockIdx.y * 32;
    int tx = threadIdx.x, ty = threadIdx.y;   // (32, 8)
    #pragma unroll
    for (int i = 0; i < 32; i += 8)
        tile[ty + i][tx] = w[(size_t)(k0 + ty + i) * N + n0 + tx];
    __syncthreads();
    #pragma unroll
    for (int i = 0; i < 32; i += 8) {
        float v = tile[tx][ty + i];
        __nv_bfloat16 h, l;
        split_bf16(v, h, l);
        th[(size_t)(n0 + ty + i) * K + k0 + tx] = h;
        tl[(size_t)(n0 + ty + i) * K + k0 + tx] = l;
    }
}

// ================= split-bf16 GEMM via mma.sync (HMMA) =================
// C[M,N] = A[M,K] @ Bt[N,K]^T (+bias)(+gelu)(+res); fp32 accum; 3-MMA split.
// CTA 256x128, 8 warps (4m x 2n), warp tile 64x64, KC=32, 3-stage cp.async.
#define KC 32
#define APAD 40                 /* bf16 elems per smem row (32 data + 8 pad) = 80B */
#define A_ROWS 256
#define B_ROWS 128
#define OFF_AH 0
#define OFF_AL (A_ROWS * APAD * 2)            /* 20480 */
#define OFF_BH (2 * A_ROWS * APAD * 2)        /* 40960 */
#define OFF_BL (OFF_BH + B_ROWS * APAD * 2)   /* 51200 */
#define STAGE_BYTES (OFF_BL + B_ROWS * APAD * 2)  /* 61440 */
#define NSTAGE 3
#define GEMM_SMEM (NSTAGE * STAGE_BYTES)      /* 184320 */

__device__ __forceinline__ void load_chunk(
    uint32_t sbase,
    const __nv_bfloat16* __restrict__ Ah, const __nv_bfloat16* __restrict__ Al,
    const __nv_bfloat16* __restrict__ Bh, const __nv_bfloat16* __restrict__ Bl,
    int m0, int n0, int K, int k0, int tid)
{
    // A: 256 rows x 4 segs x (hi,lo) = 2048 cpa16 -> 8/thread
    #pragma unroll
    for (int j = 0; j < 4; j++) {
        int idx = tid + j * 256;
        int r = idx >> 2, sg = idx & 3;
        uint32_t d = (uint32_t)(r * (APAD * 2) + sg * 16);
        size_t ga = (size_t)(m0 + r) * K + k0 + sg * 8;
        cpa16(sbase + OFF_AH + d, Ah + ga);
        cpa16(sbase + OFF_AL + d, Al + ga);
    }
    // B: 128 rows x 4 segs x (hi,lo) = 1024 cpa16 -> 4/thread
    #pragma unroll
    for (int j = 0; j < 2; j++) {
        int idx = tid + j * 256;
        int r = idx >> 2, sg = idx & 3;
        uint32_t d = (uint32_t)(r * (APAD * 2) + sg * 16);
        size_t gb = (size_t)(n0 + r) * K + k0 + sg * 8;
        cpa16(sbase + OFF_BH + d, Bh + gb);
        cpa16(sbase + OFF_BL + d, Bl + gb);
    }
}

template<bool GELU_, bool RES_, bool BF16OUT>
__global__ void __launch_bounds__(256, 1) gemm_mma(
    const __nv_bfloat16* __restrict__ Ah, const __nv_bfloat16* __restrict__ Al,
    const __nv_bfloat16* __restrict__ Bh, const __nv_bfloat16* __restrict__ Bl,
    const float* __restrict__ bias, const float* __restrict__ Res,
    float* __restrict__ Cf, __nv_bfloat16* __restrict__ Ch, __nv_bfloat16* __restrict__ Cl,
    int M, int N, int K)
{
    extern __shared__ char smem[];
    const uint32_t sb = smem_u32(smem);
    const int tid = threadIdx.x;
    const int wid = tid >> 5, lane = tid & 31;
    const int m0 = blockIdx.y * 256, n0 = blockIdx.x * 128;
    const int wm = (wid >> 1) * 64;   // 4 m-warps
    const int wn = (wid & 1) * 64;    // 2 n-warps

    // ldmatrix lane address components
    const int a_r = lane & 15;
    const int a_c = (lane & 16) ? 8 : 0;
    const int b_r = (lane & 7) + ((lane & 16) ? 8 : 0);
    const int b_c = (lane & 8) ? 8 : 0;

    float c[4][8][4];
    #pragma unroll
    for (int i = 0; i < 4; i++)
        #pragma unroll
        for (int j = 0; j < 8; j++)
            #pragma unroll
            for (int e = 0; e < 4; e++) c[i][j][e] = 0.f;

    // prologue
    load_chunk(sb, Ah, Al, Bh, Bl, m0, n0, K, 0, tid);
    cp_commit();
    load_chunk(sb + STAGE_BYTES, Ah, Al, Bh, Bl, m0, n0, K, KC, tid);
    cp_commit();

    const int NC = K / KC;
    int stage = 0;
    for (int i = 0; i < NC; i++) {
        if (i + 2 < NC) cp_wait1(); else cp_wait0();
        __syncthreads();
        if (i + 2 < NC) {
            int ls = stage + 2; if (ls >= NSTAGE) ls -= NSTAGE;
            load_chunk(sb + ls * STAGE_BYTES, Ah, Al, Bh, Bl, m0, n0, K, (i + 2) * KC, tid);
            cp_commit();
        }
        const uint32_t st = sb + stage * STAGE_BYTES;
        const uint32_t aA = st + (wm + a_r) * (APAD * 2) + a_c * 2;
        const uint32_t aB = st + (wn + b_r) * (APAD * 2) + b_c * 2;
        #pragma unroll
        for (int kk = 0; kk < KC; kk += 16) {
            uint32_t ah[4][4], al[4][4], bh[4][4], bl[4][4];
            #pragma unroll
            for (int mt = 0; mt < 4; mt++) {
                uint32_t ad = aA + mt * 16 * (APAD * 2) + kk * 2;
                ldsm_x4(ah[mt][0], ah[mt][1], ah[mt][2], ah[mt][3], ad + OFF_AH);
                ldsm_x4(al[mt][0], al[mt][1], al[mt][2], al[mt][3], ad + OFF_AL);
            }
            #pragma unroll
            for (int g = 0; g < 4; g++) {
                uint32_t bd = aB + g * 16 * (APAD * 2) + kk * 2;
                ldsm_x4(bh[g][0], bh[g][1], bh[g][2], bh[g][3], bd + OFF_BH);
                ldsm_x4(bl[g][0], bl[g][1], bl[g][2], bl[g][3], bd + OFF_BL);
            }
            #pragma unroll
            for (int mt = 0; mt < 4; mt++)
                #pragma unroll
                for (int nt = 0; nt < 8; nt++) {
                    const int g = nt >> 1, h = (nt & 1) * 2;
                    mma16816(c[mt][nt], ah[mt][0], ah[mt][1], ah[mt][2], ah[mt][3],
                             bh[g][h], bh[g][h + 1]);
                    mma16816(c[mt][nt], ah[mt][0], ah[mt][1], ah[mt][2], ah[mt][3],
                             bl[g][h], bl[g][h + 1]);
                    mma16816(c[mt][nt], al[mt][0], al[mt][1], al[mt][2], al[mt][3],
                             bh[g][h], bh[g][h + 1]);
                }
        }
        stage++; if (stage >= NSTAGE) stage = 0;
    }

    // epilogue straight from fragments
    const int t4 = lane >> 2, cp = (lane & 3) * 2;
    #pragma unroll
    for (int mt = 0; mt < 4; mt++) {
        #pragma unroll
        for (int half = 0; half < 2; half++) {
            const int row = m0 + wm + mt * 16 + t4 + half * 8;
            #pragma unroll
            for (int nt = 0; nt < 8; nt++) {
                const int col = n0 + wn + nt * 8 + cp;
                float v0 = c[mt][nt][half * 2 + 0];
                float v1 = c[mt][nt][half * 2 + 1];
                const float2 bv = *reinterpret_cast<const float2*>(bias + col);
                v0 += bv.x; v1 += bv.y;
                if (GELU_) { v0 = gelu_tanh(v0); v1 = gelu_tanh(v1); }
                if (RES_) {
                    const float2 rv = *reinterpret_cast<const float2*>(
                        Res + (size_t)row * N + col);
                    v0 += rv.x; v1 += rv.y;
                }
                const size_t oof = (size_t)row * N + col;
                if (BF16OUT) {
                    __nv_bfloat16 h0, l0, h1, l1;
                    split_bf16(v0, h0, l0); split_bf16(v1, h1, l1);
                    *reinterpret_cast<__nv_bfloat162*>(Ch + oof) = __nv_bfloat162(h0, h1);
                    *reinterpret_cast<__nv_bfloat162*>(Cl + oof) = __nv_bfloat162(l0, l1);
                } else {
                    float2 ov; ov.x = v0; ov.y = v1;
                    *reinterpret_cast<float2*>(Cf + oof) = ov;
                }
            }
        }
    }
}

// ================= Flash attention (fp32, hi/lo bf16 output) =================
#define FA_STRIDE 68

__global__ void __launch_bounds__(256) flash_attn_kernel(
    const float* __restrict__ qkv,
    __nv_bfloat16* __restrict__ ctxh, __nv_bfloat16* __restrict__ ctxl)
{
    const int qt = blockIdx.x, h = blockIdx.y, b = blockIdx.z;
    const int q0 = qt * 64;
    extern __shared__ float sm[];
    float* Qt = sm;
    float* Kt = sm + 64 * FA_STRIDE;
    float* Vs = sm + 2 * 64 * FA_STRIDE;
    float* Pt = sm + 3 * 64 * FA_STRIDE;

    const int tid = threadIdx.x;
    const int tx = tid & 15, ty = tid >> 4;
    const int lrow = tid >> 2, lq = tid & 3;

    {
        const float* qbase = qkv + ((size_t)(b * SEQ + q0) * 3) * 1024 + h * 64;
        #pragma unroll
        for (int r = 0; r < 4; r++) {
            const int d0 = (lq + r * 4) * 4;
            float4 v = *reinterpret_cast<const float4*>(qbase + (size_t)lrow * 3072 + d0);
            Qt[(d0 + 0) * FA_STRIDE + lrow] = v.x;
            Qt[(d0 + 1) * FA_STRIDE + lrow] = v.y;
            Qt[(d0 + 2) * FA_STRIDE + lrow] = v.z;
            Qt[(d0 + 3) * FA_STRIDE + lrow] = v.w;
        }
    }

    float m[4], l[4], o[4][4];
    #pragma unroll
    for (int i = 0; i < 4; i++) {
        m[i] = -1e30f; l[i] = 0.f;
        #pragma unroll
        for (int j = 0; j < 4; j++) o[i][j] = 0.f;
    }

    for (int kt = 0; kt <= qt; kt++) {
        const int k0 = kt * 64;
        __syncthreads();
        {
            const float* kbase = qkv + ((size_t)(b * SEQ + k0) * 3 + 1) * 1024 + h * 64;
            const float* vbase = qkv + ((size_t)(b * SEQ + k0) * 3 + 2) * 1024 + h * 64;
            #pragma unroll
            for (int r = 0; r < 4; r++) {
                const int d0 = (lq + r * 4) * 4;
                float4 kv = *reinterpret_cast<const float4*>(kbase + (size_t)lrow * 3072 + d0);
                Kt[(d0 + 0) * FA_STRIDE + lrow] = kv.x;
                Kt[(d0 + 1) * FA_STRIDE + lrow] = kv.y;
                Kt[(d0 + 2) * FA_STRIDE + lrow] = kv.z;
                Kt[(d0 + 3) * FA_STRIDE + lrow] = kv.w;
                float4 vv = *reinterpret_cast<const float4*>(vbase + (size_t)lrow * 3072 + d0);
                *reinterpret_cast<float4*>(&Vs[lrow * FA_STRIDE + d0]) = vv;
            }
        }
        __syncthreads();

        float s[4][4];
        #pragma unroll
        for (int i = 0; i < 4; i++)
            #pragma unroll
            for (int j = 0; j < 4; j++) s[i][j] = 0.f;
        #pragma unroll 8
        for (int d = 0; d < 64; d++) {
            float4 qv = *reinterpret_cast<float4*>(&Qt[d * FA_STRIDE + ty * 4]);
            float4 kv = *reinterpret_cast<float4*>(&Kt[d * FA_STRIDE + tx * 4]);
            float qa[4] = {qv.x, qv.y, qv.z, qv.w};
            float ka[4] = {kv.x, kv.y, kv.z, kv.w};
            #pragma unroll
            for (int i = 0; i < 4; i++)
                #pragma unroll
                for (int j = 0; j < 4; j++)
                    s[i][j] = fmaf(qa[i], ka[j], s[i][j]);
        }

        const float scale = 0.125f;
        #pragma unroll
        for (int i = 0; i < 4; i++)
            #pragma unroll
            for (int j = 0; j < 4; j++) {
                s[i][j] *= scale;
                if (kt == qt && (k0 + tx * 4 + j) > (q0 + ty * 4 + i)) s[i][j] = -1e30f;
            }

        #pragma unroll
        for (int i = 0; i < 4; i++) {
            float mx = fmaxf(fmaxf(s[i][0], s[i][1]), fmaxf(s[i][2], s[i][3]));
            #pragma unroll
            for (int off = 8; off; off >>= 1)
                mx = fmaxf(mx, __shfl_xor_sync(0xffffffffu, mx, off));
            const float mn = fmaxf(m[i], mx);
            const float alpha = __expf(m[i] - mn);
            float sum = 0.f;
            #pragma unroll
            for (int j = 0; j < 4; j++) {
                const float p = __expf(s[i][j] - mn);
                s[i][j] = p;
                sum += p;
            }
            #pragma unroll
            for (int off = 8; off; off >>= 1)
                sum += __shfl_xor_sync(0xffffffffu, sum, off);
            l[i] = l[i] * alpha + sum;
            m[i] = mn;
            #pragma unroll
            for (int j = 0; j < 4; j++) o[i][j] *= alpha;
        }

        #pragma unroll
        for (int i = 0; i < 4; i++)
            #pragma unroll
            for (int j = 0; j < 4; j++)
                Pt[(tx * 4 + j) * FA_STRIDE + ty * 4 + i] = s[i][j];
        __syncthreads();

        #pragma unroll 8
        for (int kk = 0; kk < 64; kk++) {
            float4 pv = *reinterpret_cast<float4*>(&Pt[kk * FA_STRIDE + ty * 4]);
            float4 vv = *reinterpret_cast<float4*>(&Vs[kk * FA_STRIDE + tx * 4]);
            float pa[4] = {pv.x, pv.y, pv.z, pv.w};
            float va[4] = {vv.x, vv.y, vv.z, vv.w};
            #pragma unroll
            for (int i = 0; i < 4; i++)
                #pragma unroll
                for (int j = 0; j < 4; j++)
                    o[i][j] = fmaf(pa[i], va[j], o[i][j]);
        }
    }

    // finalize: split to bf16 hi/lo directly (fuses former split_kernel)
    #pragma unroll
    for (int i = 0; i < 4; i++) {
        const float inv = 1.0f / l[i];
        const size_t oof = (size_t)(b * SEQ + q0 + ty * 4 + i) * 1024 + h * 64 + tx * 4;
        __nv_bfloat16 h0, l0, h1, l1, h2, l2, h3, l3;
        split_bf16(o[i][0] * inv, h0, l0);
        split_bf16(o[i][1] * inv, h1, l1);
        split_bf16(o[i][2] * inv, h2, l2);
        split_bf16(o[i][3] * inv, h3, l3);
        *reinterpret_cast<__nv_bfloat162*>(ctxh + oof)     = __nv_bfloat162(h0, h1);
        *reinterpret_cast<__nv_bfloat162*>(ctxh + oof + 2) = __nv_bfloat162(h2, h3);
        *reinterpret_cast<__nv_bfloat162*>(ctxl + oof)     = __nv_bfloat162(l0, l1);
        *reinterpret_cast<__nv_bfloat162*>(ctxl + oof + 2) = __nv_bfloat162(l2, l3);
    }
}

// ================= launch =================
extern "C" void kernel_launch(void* const* d_in, const int* in_sizes, int n_in,
                              void* d_out, int out_size)
{
    const float* x      = (const float*)d_in[0];
    const float* w_qkv  = (const float*)d_in[1];
    const float* b_qkv  = (const float*)d_in[2];
    const float* w_out  = (const float*)d_in[3];
    const float* b_out  = (const float*)d_in[4];
    const float* w_fc1  = (const float*)d_in[5];
    const float* b_fc1  = (const float*)d_in[6];
    const float* w_fc2  = (const float*)d_in[7];
    const float* b_fc2  = (const float*)d_in[8];
    const float* ln1s   = (const float*)d_in[9];
    const float* ln1b   = (const float*)d_in[10];
    const float* ln2s   = (const float*)d_in[11];
    const float* ln2b   = (const float*)d_in[12];
    float* out = (float*)d_out;

    float *p_qkv, *p_x1;
    __nv_bfloat16 *p_lnh, *p_lnl, *p_ctxh, *p_ctxl, *p_hh, *p_hl;
    __nv_bfloat16 *p_wqh, *p_wql, *p_woh, *p_wol, *p_w1h, *p_w1l, *p_w2h, *p_w2l;
    cudaGetSymbolAddress((void**)&p_qkv,  g_qkv);
    cudaGetSymbolAddress((void**)&p_x1,   g_x1);
    cudaGetSymbolAddress((void**)&p_lnh,  g_lnh);
    cudaGetSymbolAddress((void**)&p_lnl,  g_lnl);
    cudaGetSymbolAddress((void**)&p_ctxh, g_ctxh);
    cudaGetSymbolAddress((void**)&p_ctxl, g_ctxl);
    cudaGetSymbolAddress((void**)&p_hh,   g_hh);
    cudaGetSymbolAddress((void**)&p_hl,   g_hl);
    cudaGetSymbolAddress((void**)&p_wqh,  g_wqh);
    cudaGetSymbolAddress((void**)&p_wql,  g_wql);
    cudaGetSymbolAddress((void**)&p_woh,  g_woh);
    cudaGetSymbolAddress((void**)&p_wol,  g_wol);
    cudaGetSymbolAddress((void**)&p_w1h,  g_w1h);
    cudaGetSymbolAddress((void**)&p_w1l,  g_w1l);
    cudaGetSymbolAddress((void**)&p_w2h,  g_w2h);
    cudaGetSymbolAddress((void**)&p_w2l,  g_w2l);

    cudaFuncSetAttribute(gemm_mma<false, false, false>,
                         cudaFuncAttributeMaxDynamicSharedMemorySize, GEMM_SMEM);
    cudaFuncSetAttribute(gemm_mma<false, true, false>,
                         cudaFuncAttributeMaxDynamicSharedMemorySize, GEMM_SMEM);
    cudaFuncSetAttribute(gemm_mma<true, false, true>,
                         cudaFuncAttributeMaxDynamicSharedMemorySize, GEMM_SMEM);
    const int flash_smem = 4 * 64 * FA_STRIDE * sizeof(float);
    cudaFuncSetAttribute(flash_attn_kernel,
                         cudaFuncAttributeMaxDynamicSharedMemorySize, flash_smem);

    dim3 tb32(32, 8);
    transpose_split<<<dim3(1024 / 32, 3072 / 32), tb32>>>(w_qkv, p_wqh, p_wql, 1024, 3072);
    transpose_split<<<dim3(1024 / 32, 1024 / 32), tb32>>>(w_out, p_woh, p_wol, 1024, 1024);
    transpose_split<<<dim3(1024 / 32, 4096 / 32), tb32>>>(w_fc1, p_w1h, p_w1l, 1024, 4096);
    transpose_split<<<dim3(4096 / 32, 1024 / 32), tb32>>>(w_fc2, p_w2h, p_w2l, 4096, 1024);

    // 1) LN1 -> bf16 pair
    ln_kernel<<<MROWS, 256>>>(x, ln1s, ln1b, p_lnh, p_lnl);
    // 2) QKV projection (fp32 out)
    gemm_mma<false, false, false><<<dim3(3072 / 128, MROWS / 256), 256, GEMM_SMEM>>>(
        p_lnh, p_lnl, p_wqh, p_wql, b_qkv, nullptr, p_qkv, nullptr, nullptr,
        MROWS, 3072, 1024);
    // 3) flash attention -> bf16 hi/lo ctx
    flash_attn_kernel<<<dim3(SEQ / 64, NH, BATCH), 256, flash_smem>>>(p_qkv, p_ctxh, p_ctxl);
    // 4) out projection + residual(x)
    gemm_mma<false, true, false><<<dim3(1024 / 128, MROWS / 256), 256, GEMM_SMEM>>>(
        p_ctxh, p_ctxl, p_woh, p_wol, b_out, x, p_x1, nullptr, nullptr,
        MROWS, 1024, 1024);
    // 5) LN2 -> bf16 pair
    ln_kernel<<<MROWS, 256>>>(p_x1, ln2s, ln2b, p_lnh, p_lnl);
    // 6) FC1 + GELU -> bf16 pair
    gemm_mma<true, false, true><<<dim3(4096 / 128, MROWS / 256), 256, GEMM_SMEM>>>(
        p_lnh, p_lnl, p_w1h, p_w1l, b_fc1, nullptr, nullptr, p_hh, p_hl,
        MROWS, 4096, 1024);
    // 7) FC2 + residual(x1) -> out
    gemm_mma<false, true, false><<<dim3(1024 / 128, MROWS / 256), 256, GEMM_SMEM>>>(
        p_hh, p_hl, p_w2h, p_w2l, b_fc2, p_x1, out, nullptr, nullptr,
        MROWS, 1024, 4096);
}